// round 1
// baseline (speedup 1.0000x reference)
#include <cuda_runtime.h>
#include <cuda_bf16.h>

// ---------------------------------------------------------------------------
// PAConv fused pipeline, fp32 SIMT baseline.
// Shapes: B=4, N=4096, K=32, Cin=Cout=64, m=8, P=B*N*K=524288, Q=B*N=16384.
// ---------------------------------------------------------------------------

#define Pn   524288          // B*N*K
#define Qn   16384           // B*N
#define NB   4096            // N
#define EPS  1e-5f

// ---- scratch (static device globals; no allocations allowed) --------------
__device__ float g_s0[64u * 524288u];     // ScoreNet layer0 raw   (134 MB)
__device__ float g_s1[32u * 524288u];     // layer1 raw            (67 MB)
__device__ float g_s2[16u * 524288u];     // layer2 raw            (33.5 MB)
__device__ float g_score[524288u * 8u];   // softmaxed scores [p][m]
__device__ float g_h[64u * 16384u];       // conv1 raw, layout [c][q]
__device__ float g_y[16384u * 512u];      // y, layout [q][m*64+o]
__device__ float g_outraw[4u * 64u * 4096u];
__device__ float g_stats[512];            // sums / sumsqs
__device__ float g_ab[512];               // scale(a) / shift(b) per BN group

// stats / ab segment offsets:  bn1: 0/64   sn0: 128/192   sn1: 256/288
//                              sn2: 320/336   bn2: 352/416

// ---------------------------------------------------------------------------
// zero the stat accumulators (must re-run every graph replay)
__global__ void zero_stats(float* st) {
    if (threadIdx.x < 512) st[threadIdx.x] = 0.f;
}

// ---------------------------------------------------------------------------
// Generic channel-major GEMM:  out[o*P + p] = sum_c W[o*C+c] * act(in(c,p))
// in(c,p) = in[b*BS + c*PB + (p - b*PB)],  b = p / PB  (tile never crosses b)
// act: relu(a[c]*v + b[c]) with a=ab[c], b=ab[C+c] when ACT.
// 256 threads, 128-wide p tile, micro-tile TO x 4.
template<int C, int O, bool ACT>
__global__ __launch_bounds__(256) void gemm_cp(
    const float* __restrict__ in, const float* __restrict__ W,
    const float* __restrict__ ab, float* __restrict__ out,
    int P, int PB, long BS)
{
    constexpr int TO = O / 8;
    extern __shared__ float sm[];
    float* Wt  = sm;               // [C][O] transposed
    float* a_s = sm + C * O;       // [C]
    float* b_s = a_s + C;          // [C]
    float* ins = b_s + C;          // [C][128]

    const int tid = threadIdx.x;
    const int p0  = blockIdx.x * 128;
    const int b0  = p0 / PB;
    const long ibase = (long)b0 * BS + (long)(p0 - b0 * PB);

    for (int i = tid; i < C * O; i += 256) {
        int o = i / C, c = i - o * C;
        Wt[c * O + o] = W[i];
    }
    if (ACT) {
        if (tid < C) { a_s[tid] = ab[tid]; b_s[tid] = ab[C + tid]; }
    }
    __syncthreads();

    for (int i = tid; i < C * 128; i += 256) {
        int c = i >> 7, pl = i & 127;
        float v = in[ibase + (long)c * PB + pl];
        if (ACT) v = fmaxf(fmaf(a_s[c], v, b_s[c]), 0.f);
        ins[i] = v;
    }
    __syncthreads();

    const int og = (tid & 7) * TO;
    const int pb = (tid >> 3) * 4;

    float acc[TO][4];
    #pragma unroll
    for (int j = 0; j < TO; j++)
        #pragma unroll
        for (int t = 0; t < 4; t++) acc[j][t] = 0.f;

    #pragma unroll 4
    for (int c = 0; c < C; c++) {
        float wv[TO], iv[4];
        #pragma unroll
        for (int j = 0; j < TO; j++) wv[j] = Wt[c * O + og + j];
        #pragma unroll
        for (int t = 0; t < 4; t++)  iv[t] = ins[c * 128 + pb + t];
        #pragma unroll
        for (int j = 0; j < TO; j++)
            #pragma unroll
            for (int t = 0; t < 4; t++)
                acc[j][t] = fmaf(wv[j], iv[t], acc[j][t]);
    }

    #pragma unroll
    for (int j = 0; j < TO; j++) {
        float4 v = make_float4(acc[j][0], acc[j][1], acc[j][2], acc[j][3]);
        *reinterpret_cast<float4*>(out + (size_t)(og + j) * P + p0 + pb) = v;
    }
}

// ---------------------------------------------------------------------------
// per-channel sum / sumsq over channel-major buffer s[c*P + p]
__global__ __launch_bounds__(256) void stats_cp(
    const float* __restrict__ s, float* __restrict__ sum, float* __restrict__ sq,
    int P, int perblock)
{
    const int c = blockIdx.y;
    const size_t base = (size_t)c * P + (size_t)blockIdx.x * perblock;
    float ls = 0.f, lq = 0.f;
    for (int i = threadIdx.x * 4; i < perblock; i += 256 * 4) {
        float4 v = *reinterpret_cast<const float4*>(s + base + i);
        ls += (v.x + v.y) + (v.z + v.w);
        lq += v.x * v.x + v.y * v.y + v.z * v.z + v.w * v.w;
    }
    #pragma unroll
    for (int o = 16; o; o >>= 1) {
        ls += __shfl_xor_sync(0xffffffffu, ls, o);
        lq += __shfl_xor_sync(0xffffffffu, lq, o);
    }
    __shared__ float ws[8], wq[8];
    if ((threadIdx.x & 31) == 0) { ws[threadIdx.x >> 5] = ls; wq[threadIdx.x >> 5] = lq; }
    __syncthreads();
    if (threadIdx.x == 0) {
        float a = 0.f, b = 0.f;
        #pragma unroll
        for (int i = 0; i < 8; i++) { a += ws[i]; b += wq[i]; }
        atomicAdd(sum + c, a);
        atomicAdd(sq + c, b);
    }
}

// stats for out_raw layout [b][o][n]  (channel = o, reduced over b,n)
__global__ __launch_bounds__(256) void stats_bon(
    const float* __restrict__ outr, float* __restrict__ sum, float* __restrict__ sq)
{
    const int o = blockIdx.x, b = blockIdx.y;
    const float* ptr = outr + ((size_t)b * 64 + o) * NB;
    float ls = 0.f, lq = 0.f;
    for (int i = threadIdx.x * 4; i < NB; i += 256 * 4) {
        float4 v = *reinterpret_cast<const float4*>(ptr + i);
        ls += (v.x + v.y) + (v.z + v.w);
        lq += v.x * v.x + v.y * v.y + v.z * v.z + v.w * v.w;
    }
    #pragma unroll
    for (int s = 16; s; s >>= 1) {
        ls += __shfl_xor_sync(0xffffffffu, ls, s);
        lq += __shfl_xor_sync(0xffffffffu, lq, s);
    }
    __shared__ float ws[8], wq[8];
    if ((threadIdx.x & 31) == 0) { ws[threadIdx.x >> 5] = ls; wq[threadIdx.x >> 5] = lq; }
    __syncthreads();
    if (threadIdx.x == 0) {
        float a = 0.f, c2 = 0.f;
        #pragma unroll
        for (int i = 0; i < 8; i++) { a += ws[i]; c2 += wq[i]; }
        atomicAdd(sum + o, a);
        atomicAdd(sq + o, c2);
    }
}

// convert (sum,sumsq,gamma,beta) -> (scale a, shift b)
__global__ void finalize_bn(
    const float* __restrict__ sum, const float* __restrict__ sq,
    const float* __restrict__ gam, const float* __restrict__ bet,
    float* __restrict__ ab, int C, float inv)
{
    int c = threadIdx.x;
    if (c < C) {
        float m   = sum[c] * inv;
        float var = sq[c] * inv - m * m;
        float s   = gam[c] * rsqrtf(var + EPS);
        ab[c]     = s;
        ab[C + c] = bet[c] - m * s;
    }
}

// ---------------------------------------------------------------------------
// y GEMM:  y[q][k2] = sum_c relu(a1*h[c][q]+b1) * M2[c][k2]
// tile 128q x 64k2, 256 threads, micro 4q x 8k2
__global__ __launch_bounds__(256) void ygemm(
    const float* __restrict__ h, const float* __restrict__ M2,
    const float* __restrict__ ab, float* __restrict__ y)
{
    extern __shared__ float sm[];
    float* As  = sm;               // [64][128]
    float* Bs  = sm + 64 * 128;    // [64][64]
    float* a_s = Bs + 64 * 64;
    float* b_s = a_s + 64;

    const int tid = threadIdx.x;
    const int q0  = blockIdx.x * 128;
    const int k20 = blockIdx.y * 64;

    if (tid < 64) { a_s[tid] = ab[tid]; b_s[tid] = ab[64 + tid]; }
    __syncthreads();

    for (int i = tid; i < 64 * 128; i += 256) {
        int c = i >> 7, ql = i & 127;
        float v = h[c * Qn + q0 + ql];
        As[i] = fmaxf(fmaf(a_s[c], v, b_s[c]), 0.f);
    }
    for (int i = tid; i < 64 * 64; i += 256) {
        int c = i >> 6, j = i & 63;
        Bs[i] = M2[c * 512 + k20 + j];
    }
    __syncthreads();

    const int kb = (tid & 7) * 8;
    const int qb = (tid >> 3) * 4;
    float acc[4][8];
    #pragma unroll
    for (int t = 0; t < 4; t++)
        #pragma unroll
        for (int j = 0; j < 8; j++) acc[t][j] = 0.f;

    #pragma unroll 4
    for (int c = 0; c < 64; c++) {
        float av[4], bv[8];
        #pragma unroll
        for (int t = 0; t < 4; t++) av[t] = As[c * 128 + qb + t];
        #pragma unroll
        for (int j = 0; j < 8; j++) bv[j] = Bs[c * 64 + kb + j];
        #pragma unroll
        for (int t = 0; t < 4; t++)
            #pragma unroll
            for (int j = 0; j < 8; j++)
                acc[t][j] = fmaf(av[t], bv[j], acc[t][j]);
    }

    #pragma unroll
    for (int t = 0; t < 4; t++) {
        float* dst = y + (size_t)(q0 + qb + t) * 512 + k20 + kb;
        *reinterpret_cast<float4*>(dst)     = make_float4(acc[t][0], acc[t][1], acc[t][2], acc[t][3]);
        *reinterpret_cast<float4*>(dst + 4) = make_float4(acc[t][4], acc[t][5], acc[t][6], acc[t][7]);
    }
}

// ---------------------------------------------------------------------------
// ScoreNet layer3 (16 -> 8) + bias + softmax over m; writes score[p][m]
__global__ __launch_bounds__(256) void l3_softmax(
    const float* __restrict__ s2, const float* __restrict__ w3,
    const float* __restrict__ bias3, const float* __restrict__ ab,
    float* __restrict__ score)
{
    __shared__ float W[128], B3[8], A2[16], B2[16];
    const int tid = threadIdx.x;
    if (tid < 128) W[tid] = w3[tid];
    if (tid < 8)   B3[tid] = bias3[tid];
    if (tid < 16)  { A2[tid] = ab[tid]; B2[tid] = ab[16 + tid]; }
    __syncthreads();

    const int p = blockIdx.x * 256 + tid;
    float v[16];
    #pragma unroll
    for (int c = 0; c < 16; c++) {
        float raw = s2[(size_t)c * Pn + p];
        v[c] = fmaxf(fmaf(A2[c], raw, B2[c]), 0.f);
    }
    float z[8];
    #pragma unroll
    for (int mi = 0; mi < 8; mi++) {
        float acc = B3[mi];
        #pragma unroll
        for (int c = 0; c < 16; c++) acc = fmaf(W[mi * 16 + c], v[c], acc);
        z[mi] = acc;
    }
    float mx = z[0];
    #pragma unroll
    for (int mi = 1; mi < 8; mi++) mx = fmaxf(mx, z[mi]);
    float se = 0.f;
    #pragma unroll
    for (int mi = 0; mi < 8; mi++) { z[mi] = __expf(z[mi] - mx); se += z[mi]; }
    float inv = 1.f / se;
    float* dst = score + (size_t)p * 8;
    *reinterpret_cast<float4*>(dst)     = make_float4(z[0]*inv, z[1]*inv, z[2]*inv, z[3]*inv);
    *reinterpret_cast<float4*>(dst + 4) = make_float4(z[4]*inv, z[5]*inv, z[6]*inv, z[7]*inv);
}

// ---------------------------------------------------------------------------
// gather + weighted sum:  out_raw[b][o][n] = sum_{k,m} score[q,k,m] * y[b,idx,m,o]
// one block per (b,n), thread = o. ~64 KB of (mostly L2-hit) reads per block.
__global__ __launch_bounds__(64) void gather_k(
    const float* __restrict__ y, const float* __restrict__ score,
    const int* __restrict__ idx, float* __restrict__ outr)
{
    __shared__ int id[32];
    __shared__ __align__(16) float sc[32][8];
    const int q   = blockIdx.x;           // b*N + n
    const int tid = threadIdx.x;          // = o
    const int b   = q >> 12;
    const int n   = q & 4095;

    if (tid < 32) id[tid] = idx[(size_t)q * 32 + tid];
    reinterpret_cast<float4*>(sc)[tid] =
        reinterpret_cast<const float4*>(score + (size_t)q * 256)[tid];
    __syncthreads();

    float acc0 = 0.f, acc1 = 0.f;
    #pragma unroll 2
    for (int k = 0; k < 32; k++) {
        const float* yr = y + ((size_t)(b << 12) + id[k]) * 512 + tid;
        float4 sA = *reinterpret_cast<const float4*>(&sc[k][0]);
        float4 sB = *reinterpret_cast<const float4*>(&sc[k][4]);
        acc0 = fmaf(sA.x, yr[0 * 64], acc0);
        acc1 = fmaf(sA.y, yr[1 * 64], acc1);
        acc0 = fmaf(sA.z, yr[2 * 64], acc0);
        acc1 = fmaf(sA.w, yr[3 * 64], acc1);
        acc0 = fmaf(sB.x, yr[4 * 64], acc0);
        acc1 = fmaf(sB.y, yr[5 * 64], acc1);
        acc0 = fmaf(sB.z, yr[6 * 64], acc0);
        acc1 = fmaf(sB.w, yr[7 * 64], acc1);
    }
    outr[((size_t)(b * 64 + tid)) * NB + n] = acc0 + acc1;
}

// final bn2 + relu, elementwise over (B,64,N) in output layout
__global__ __launch_bounds__(256) void apply_bn2(
    const float* __restrict__ outr, const float* __restrict__ ab,
    float* __restrict__ out)
{
    int i = blockIdx.x * 256 + threadIdx.x;
    int o = (i >> 12) & 63;
    out[i] = fmaxf(fmaf(ab[o], outr[i], ab[64 + o]), 0.f);
}

// ---------------------------------------------------------------------------
extern "C" void kernel_launch(void* const* d_in, const int* in_sizes, int n_in,
                              void* d_out, int out_size)
{
    const float* x     = (const float*)d_in[0];
    const float* xyz   = (const float*)d_in[1];
    const float* w1    = (const float*)d_in[2];
    const float* bn1g  = (const float*)d_in[3];
    const float* bn1b  = (const float*)d_in[4];
    const float* m2    = (const float*)d_in[5];
    const float* sw0   = (const float*)d_in[6];
    const float* sg0   = (const float*)d_in[7];
    const float* sb0   = (const float*)d_in[8];
    const float* sw1   = (const float*)d_in[9];
    const float* sg1   = (const float*)d_in[10];
    const float* sb1   = (const float*)d_in[11];
    const float* sw2   = (const float*)d_in[12];
    const float* sg2   = (const float*)d_in[13];
    const float* sb2   = (const float*)d_in[14];
    const float* sw3   = (const float*)d_in[15];
    const float* sbs3  = (const float*)d_in[16];
    const float* bn2g  = (const float*)d_in[17];
    const float* bn2b  = (const float*)d_in[18];
    const int*   idx   = (const int*)d_in[19];
    float* out = (float*)d_out;

    float *s0, *s1, *s2, *score, *h, *y, *outr, *st, *ab;
    cudaGetSymbolAddress((void**)&s0,    g_s0);
    cudaGetSymbolAddress((void**)&s1,    g_s1);
    cudaGetSymbolAddress((void**)&s2,    g_s2);
    cudaGetSymbolAddress((void**)&score, g_score);
    cudaGetSymbolAddress((void**)&h,     g_h);
    cudaGetSymbolAddress((void**)&y,     g_y);
    cudaGetSymbolAddress((void**)&outr,  g_outraw);
    cudaGetSymbolAddress((void**)&st,    g_stats);
    cudaGetSymbolAddress((void**)&ab,    g_ab);

    // dynamic smem sizes (some exceed the 48KB static limit)
    const int sm_l0 = (66*64 + 2*66 + 66*128) * 4;   // 51216
    const int sm_cv = (64*64 + 2*64 + 64*128) * 4;   // 49664
    const int sm_l1 = (64*32 + 2*64 + 64*128) * 4;   // 41472
    const int sm_l2 = (32*16 + 2*32 + 32*128) * 4;   // 18688
    const int sm_yg = (64*128 + 64*64 + 2*64) * 4;   // 49664
    cudaFuncSetAttribute((const void*)gemm_cp<66,64,false>, cudaFuncAttributeMaxDynamicSharedMemorySize, sm_l0);
    cudaFuncSetAttribute((const void*)gemm_cp<64,64,false>, cudaFuncAttributeMaxDynamicSharedMemorySize, sm_cv);
    cudaFuncSetAttribute((const void*)gemm_cp<64,32,true>,  cudaFuncAttributeMaxDynamicSharedMemorySize, sm_l1);
    cudaFuncSetAttribute((const void*)gemm_cp<32,16,true>,  cudaFuncAttributeMaxDynamicSharedMemorySize, sm_l2);
    cudaFuncSetAttribute((const void*)ygemm,                cudaFuncAttributeMaxDynamicSharedMemorySize, sm_yg);

    const float invP = 1.f / (float)Pn;
    const float invQ = 1.f / (float)Qn;

    zero_stats<<<1, 512>>>(st);

    // ---- ScoreNet chain (run first so y stays L2-hot for the gather) ----
    gemm_cp<66,64,false><<<Pn/128, 256, sm_l0>>>(xyz, sw0, nullptr, s0,
                                                 Pn, 131072, 66L*131072);
    stats_cp<<<dim3(64, 64), 256>>>(s0, st + 128, st + 192, Pn, 8192);
    finalize_bn<<<1, 64>>>(st + 128, st + 192, sg0, sb0, ab + 128, 64, invP);

    gemm_cp<64,32,true><<<Pn/128, 256, sm_l1>>>(s0, sw1, ab + 128, s1,
                                                Pn, Pn, 0L);
    stats_cp<<<dim3(64, 32), 256>>>(s1, st + 256, st + 288, Pn, 8192);
    finalize_bn<<<1, 32>>>(st + 256, st + 288, sg1, sb1, ab + 256, 32, invP);

    gemm_cp<32,16,true><<<Pn/128, 256, sm_l2>>>(s1, sw2, ab + 256, s2,
                                                Pn, Pn, 0L);
    stats_cp<<<dim3(64, 16), 256>>>(s2, st + 320, st + 336, Pn, 8192);
    finalize_bn<<<1, 16>>>(st + 320, st + 336, sg2, sb2, ab + 320, 16, invP);

    l3_softmax<<<Pn/256, 256>>>(s2, sw3, sbs3, ab + 320, score);

    // ---- main path: conv1 -> bn1 stats -> y GEMM ----
    gemm_cp<64,64,false><<<Qn/128, 256, sm_cv>>>(x, w1, nullptr, h,
                                                 Qn, 4096, 64L*4096);
    stats_cp<<<dim3(2, 64), 256>>>(h, st + 0, st + 64, Qn, 8192);
    finalize_bn<<<1, 64>>>(st + 0, st + 64, bn1g, bn1b, ab + 0, 64, invQ);

    ygemm<<<dim3(Qn/128, 8), 256, sm_yg>>>(h, m2, ab + 0, y);

    // ---- gather + weighted sum (y fresh in L2) ----
    gather_k<<<Qn, 64>>>(y, score, idx, outr);

    // ---- final bn2 + relu ----
    stats_bon<<<dim3(64, 4), 256>>>(outr, st + 352, st + 416);
    finalize_bn<<<1, 64>>>(st + 352, st + 416, bn2g, bn2b, ab + 352, 64, invQ);
    apply_bn2<<<4096, 256>>>(outr, ab + 352, out);
}

// round 4
// speedup vs baseline: 1.0971x; 1.0971x over previous
#include <cuda_runtime.h>
#include <cuda_bf16.h>

// ---------------------------------------------------------------------------
// PAConv fused pipeline v3: f32x2 packed FMA, fused BN stats, fp32 scratch.
// Shapes: B=4, N=4096, K=32, Cin=Cout=64, m=8, P=B*N*K=524288, Q=B*N=16384.
// ---------------------------------------------------------------------------

#define Pn   524288
#define Qn   16384
#define NB   4096
#define EPS  1e-5f

typedef unsigned long long ull;

// ---- scratch -------------------------------------------------------------
__device__ float g_s0[64u * 524288u];     // layer0 raw   (134 MB)
__device__ float g_s1[32u * 524288u];     // layer1 raw   (67 MB)
__device__ float g_s2[16u * 524288u];     // layer2 raw   (33.5 MB)
__device__ float g_score[524288u * 8u];   // softmaxed scores [p][m]
__device__ float g_h[64u * 16384u];       // conv1 raw [c][q]
__device__ float g_y[16384u * 512u];      // y [q][m*64+o]
__device__ float g_outraw[4u * 64u * 4096u];
__device__ float g_stats[512];
__device__ float g_ab[512];
// stats/ab offsets:  bn1 0/64 | sn0 128/192 | sn1 256/288 | sn2 320/336 | bn2 352/416

// ---- f32x2 helpers -------------------------------------------------------
__device__ __forceinline__ ull dup2(float v) {
    ull r; asm("mov.b64 %0, {%1, %1};" : "=l"(r) : "f"(v)); return r;
}
__device__ __forceinline__ void fma2(ull& d, ull a, ull b) {
    asm("fma.rn.f32x2 %0, %1, %2, %0;" : "+l"(d) : "l"(a), "l"(b));
}
__device__ __forceinline__ float2 unpk(ull v) {
    float2 r; asm("mov.b64 {%0, %1}, %2;" : "=f"(r.x), "=f"(r.y) : "l"(v)); return r;
}

__global__ void zero_stats(float* st) {
    if (threadIdx.x < 512) st[threadIdx.x] = 0.f;
}

// ---------------------------------------------------------------------------
// GEMM: out[o*P + p] = sum_c W[o*C+c] * act(in(c,p)),  fused per-channel stats.
// in(c,p) = in[b*BS + c*PB + (p - b*PB)], b = p0 / PB (256-tile never crosses b)
// 256 threads, 256-pt tile; warp w owns channels [w*TO, w*TO+TO), lane owns 8 pts.
template<int C, int O, bool ACT>
__global__ __launch_bounds__(256, 2) void gemm2(
    const float* __restrict__ in, const float* __restrict__ W,
    const float* __restrict__ ab, float* __restrict__ out,
    float* __restrict__ sum, float* __restrict__ sq,
    int P, int PB, long BS)
{
    constexpr int TO = O / 8;
    extern __shared__ float sm[];
    float* Wt  = sm;              // [C][O]
    float* ins = sm + C * O;      // [C][256]

    const int tid  = threadIdx.x;
    const int lane = tid & 31;
    const int wid  = tid >> 5;
    const int p0   = blockIdx.x * 256;
    const int b0   = p0 / PB;
    const long ibase = (long)b0 * BS + (long)(p0 - b0 * PB);

    for (int i = tid; i < C * O; i += 256) {
        int o = i / C, c = i - o * C;
        Wt[c * O + o] = W[i];
    }

    // stage 256 points x C channels (4 elems / thread-iter)
    for (int i = tid; i < C * 64; i += 256) {
        int c  = i >> 6;
        int p4 = (i & 63) << 2;
        float4 v = *reinterpret_cast<const float4*>(in + ibase + (long)c * PB + p4);
        if (ACT) {
            float a = ab[c], b = ab[C + c];
            v.x = fmaxf(fmaf(a, v.x, b), 0.f);
            v.y = fmaxf(fmaf(a, v.y, b), 0.f);
            v.z = fmaxf(fmaf(a, v.z, b), 0.f);
            v.w = fmaxf(fmaf(a, v.w, b), 0.f);
        }
        *reinterpret_cast<float4*>(ins + c * 256 + p4) = v;
    }
    __syncthreads();

    const int o0 = wid * TO;
    ull acc[TO][4];
    #pragma unroll
    for (int j = 0; j < TO; j++)
        #pragma unroll
        for (int t = 0; t < 4; t++) acc[j][t] = 0ull;

    #pragma unroll 2
    for (int c = 0; c < C; c++) {
        ull wv[TO];
        #pragma unroll
        for (int j = 0; j < TO; j++) wv[j] = dup2(Wt[c * O + o0 + j]);
        const ulonglong2* ip = reinterpret_cast<const ulonglong2*>(ins + c * 256 + lane * 8);
        ulonglong2 pa = ip[0], pb = ip[1];
        ull pv[4] = { pa.x, pa.y, pb.x, pb.y };
        #pragma unroll
        for (int j = 0; j < TO; j++)
            #pragma unroll
            for (int t = 0; t < 4; t++)
                fma2(acc[j][t], wv[j], pv[t]);
    }

    // epilogue: store + per-channel stats (warp owns disjoint channels)
    #pragma unroll
    for (int j = 0; j < TO; j++) {
        float2 f[4];
        float s = 0.f, q = 0.f;
        #pragma unroll
        for (int t = 0; t < 4; t++) {
            f[t] = unpk(acc[j][t]);
            s += f[t].x + f[t].y;
            q += f[t].x * f[t].x + f[t].y * f[t].y;
        }
        float* dst = out + (size_t)(o0 + j) * P + p0 + lane * 8;
        *reinterpret_cast<float4*>(dst)     = make_float4(f[0].x, f[0].y, f[1].x, f[1].y);
        *reinterpret_cast<float4*>(dst + 4) = make_float4(f[2].x, f[2].y, f[3].x, f[3].y);
        #pragma unroll
        for (int o = 16; o; o >>= 1) {
            s += __shfl_xor_sync(0xffffffffu, s, o);
            q += __shfl_xor_sync(0xffffffffu, q, o);
        }
        if (lane == 0) {
            atomicAdd(sum + o0 + j, s);
            atomicAdd(sq  + o0 + j, q);
        }
    }
}

// ---------------------------------------------------------------------------
__global__ void finalize_bn(
    const float* __restrict__ sum, const float* __restrict__ sq,
    const float* __restrict__ gam, const float* __restrict__ bet,
    float* __restrict__ ab, int C, float inv)
{
    int c = threadIdx.x;
    if (c < C) {
        float m   = sum[c] * inv;
        float var = sq[c] * inv - m * m;
        float s   = gam[c] * rsqrtf(var + EPS);
        ab[c]     = s;
        ab[C + c] = bet[c] - m * s;
    }
}

// ---------------------------------------------------------------------------
// y GEMM: y[q][k2] = sum_c relu(a1*h[c][q]+b1) * M2[c][k2]; 128q x 64k2 tile.
__global__ __launch_bounds__(256) void ygemm(
    const float* __restrict__ h, const float* __restrict__ M2,
    const float* __restrict__ ab, float* __restrict__ y)
{
    extern __shared__ float sm[];
    float* As = sm;               // [64][128]
    float* Bs = sm + 64 * 128;    // [64][64]

    const int tid = threadIdx.x;
    const int q0  = blockIdx.x * 128;
    const int k20 = blockIdx.y * 64;

    for (int i = tid; i < 64 * 128; i += 256) {
        int c = i >> 7, ql = i & 127;
        float v = h[c * Qn + q0 + ql];
        As[i] = fmaxf(fmaf(ab[c], v, ab[64 + c]), 0.f);
    }
    for (int i = tid; i < 64 * 64; i += 256) {
        int c = i >> 6, j = i & 63;
        Bs[i] = M2[c * 512 + k20 + j];
    }
    __syncthreads();

    const int kb = (tid & 7) * 8;
    const int qb = (tid >> 3) * 4;
    ull acc[2][8];
    #pragma unroll
    for (int t = 0; t < 2; t++)
        #pragma unroll
        for (int j = 0; j < 8; j++) acc[t][j] = 0ull;

    #pragma unroll 2
    for (int c = 0; c < 64; c++) {
        ulonglong2 ap = *reinterpret_cast<const ulonglong2*>(As + c * 128 + qb);
        ull av[2] = { ap.x, ap.y };
        ull bv[8];
        #pragma unroll
        for (int j = 0; j < 8; j++) bv[j] = dup2(Bs[c * 64 + kb + j]);
        #pragma unroll
        for (int t = 0; t < 2; t++)
            #pragma unroll
            for (int j = 0; j < 8; j++)
                fma2(acc[t][j], av[t], bv[j]);
    }

    #pragma unroll
    for (int t = 0; t < 2; t++) {
        float r0[8], r1[8];
        #pragma unroll
        for (int j = 0; j < 8; j++) {
            float2 f = unpk(acc[t][j]);
            r0[j] = f.x; r1[j] = f.y;
        }
        float* d0 = y + (size_t)(q0 + qb + 2 * t) * 512 + k20 + kb;
        float* d1 = d0 + 512;
        *reinterpret_cast<float4*>(d0)     = make_float4(r0[0], r0[1], r0[2], r0[3]);
        *reinterpret_cast<float4*>(d0 + 4) = make_float4(r0[4], r0[5], r0[6], r0[7]);
        *reinterpret_cast<float4*>(d1)     = make_float4(r1[0], r1[1], r1[2], r1[3]);
        *reinterpret_cast<float4*>(d1 + 4) = make_float4(r1[4], r1[5], r1[6], r1[7]);
    }
}

// ---------------------------------------------------------------------------
// ScoreNet layer3 (16 -> 8) + bias + softmax over m
__global__ __launch_bounds__(256) void l3_softmax(
    const float* __restrict__ s2, const float* __restrict__ w3,
    const float* __restrict__ bias3, const float* __restrict__ ab,
    float* __restrict__ score)
{
    __shared__ float W[128], B3[8], A2[16], B2[16];
    const int tid = threadIdx.x;
    if (tid < 128) W[tid] = w3[tid];
    if (tid < 8)   B3[tid] = bias3[tid];
    if (tid < 16)  { A2[tid] = ab[tid]; B2[tid] = ab[16 + tid]; }
    __syncthreads();

    const int p = blockIdx.x * 256 + tid;
    float v[16];
    #pragma unroll
    for (int c = 0; c < 16; c++) {
        float raw = s2[(size_t)c * Pn + p];
        v[c] = fmaxf(fmaf(A2[c], raw, B2[c]), 0.f);
    }
    float z[8];
    #pragma unroll
    for (int mi = 0; mi < 8; mi++) {
        float acc = B3[mi];
        #pragma unroll
        for (int c = 0; c < 16; c++) acc = fmaf(W[mi * 16 + c], v[c], acc);
        z[mi] = acc;
    }
    float mx = z[0];
    #pragma unroll
    for (int mi = 1; mi < 8; mi++) mx = fmaxf(mx, z[mi]);
    float se = 0.f;
    #pragma unroll
    for (int mi = 0; mi < 8; mi++) { z[mi] = __expf(z[mi] - mx); se += z[mi]; }
    float inv = 1.f / se;
    float* dst = score + (size_t)p * 8;
    *reinterpret_cast<float4*>(dst)     = make_float4(z[0]*inv, z[1]*inv, z[2]*inv, z[3]*inv);
    *reinterpret_cast<float4*>(dst + 4) = make_float4(z[4]*inv, z[5]*inv, z[6]*inv, z[7]*inv);
}

// ---------------------------------------------------------------------------
// gather + weighted sum + fused bn2 stats
__global__ __launch_bounds__(64) void gather_k(
    const float* __restrict__ y, const float* __restrict__ score,
    const int* __restrict__ idx, float* __restrict__ outr,
    float* __restrict__ sum, float* __restrict__ sq)
{
    __shared__ int id[32];
    __shared__ __align__(16) float sc[32][8];
    const int q   = blockIdx.x;
    const int tid = threadIdx.x;          // = o
    const int b   = q >> 12;
    const int n   = q & 4095;

    if (tid < 32) id[tid] = idx[(size_t)q * 32 + tid];
    reinterpret_cast<float4*>(sc)[tid] =
        reinterpret_cast<const float4*>(score + (size_t)q * 256)[tid];
    __syncthreads();

    float acc0 = 0.f, acc1 = 0.f;
    #pragma unroll 2
    for (int k = 0; k < 32; k++) {
        const float* yr = y + ((size_t)(b << 12) + id[k]) * 512 + tid;
        float4 sA = *reinterpret_cast<const float4*>(&sc[k][0]);
        float4 sB = *reinterpret_cast<const float4*>(&sc[k][4]);
        acc0 = fmaf(sA.x, yr[0 * 64], acc0);
        acc1 = fmaf(sA.y, yr[1 * 64], acc1);
        acc0 = fmaf(sA.z, yr[2 * 64], acc0);
        acc1 = fmaf(sA.w, yr[3 * 64], acc1);
        acc0 = fmaf(sB.x, yr[4 * 64], acc0);
        acc1 = fmaf(sB.y, yr[5 * 64], acc1);
        acc0 = fmaf(sB.z, yr[6 * 64], acc0);
        acc1 = fmaf(sB.w, yr[7 * 64], acc1);
    }
    float v = acc0 + acc1;
    outr[((size_t)(b * 64 + tid)) * NB + n] = v;
    atomicAdd(sum + tid, v);
    atomicAdd(sq  + tid, v * v);
}

__global__ __launch_bounds__(256) void apply_bn2(
    const float* __restrict__ outr, const float* __restrict__ ab,
    float* __restrict__ out)
{
    int i = blockIdx.x * 256 + threadIdx.x;
    int o = (i >> 12) & 63;
    out[i] = fmaxf(fmaf(ab[o], outr[i], ab[64 + o]), 0.f);
}

// ---------------------------------------------------------------------------
extern "C" void kernel_launch(void* const* d_in, const int* in_sizes, int n_in,
                              void* d_out, int out_size)
{
    const float* x     = (const float*)d_in[0];
    const float* xyz   = (const float*)d_in[1];
    const float* w1    = (const float*)d_in[2];
    const float* bn1g  = (const float*)d_in[3];
    const float* bn1b  = (const float*)d_in[4];
    const float* m2    = (const float*)d_in[5];
    const float* sw0   = (const float*)d_in[6];
    const float* sg0   = (const float*)d_in[7];
    const float* sb0   = (const float*)d_in[8];
    const float* sw1   = (const float*)d_in[9];
    const float* sg1   = (const float*)d_in[10];
    const float* sb1   = (const float*)d_in[11];
    const float* sw2   = (const float*)d_in[12];
    const float* sg2   = (const float*)d_in[13];
    const float* sb2   = (const float*)d_in[14];
    const float* sw3   = (const float*)d_in[15];
    const float* sbs3  = (const float*)d_in[16];
    const float* bn2g  = (const float*)d_in[17];
    const float* bn2b  = (const float*)d_in[18];
    const int*   idx   = (const int*)d_in[19];
    float* out = (float*)d_out;

    float *s0, *s1, *s2, *score, *h, *y, *outr, *st, *ab;
    cudaGetSymbolAddress((void**)&s0,    g_s0);
    cudaGetSymbolAddress((void**)&s1,    g_s1);
    cudaGetSymbolAddress((void**)&s2,    g_s2);
    cudaGetSymbolAddress((void**)&score, g_score);
    cudaGetSymbolAddress((void**)&h,     g_h);
    cudaGetSymbolAddress((void**)&y,     g_y);
    cudaGetSymbolAddress((void**)&outr,  g_outraw);
    cudaGetSymbolAddress((void**)&st,    g_stats);
    cudaGetSymbolAddress((void**)&ab,    g_ab);

    const int sm_l0 = (66*64 + 66*256) * 4;   // 84480
    const int sm_cv = (64*64 + 64*256) * 4;   // 81920
    const int sm_l1 = (64*32 + 64*256) * 4;   // 73728
    const int sm_l2 = (32*16 + 32*256) * 4;   // 34816
    const int sm_yg = (64*128 + 64*64) * 4;   // 49152
    cudaFuncSetAttribute((const void*)gemm2<66,64,false>, cudaFuncAttributeMaxDynamicSharedMemorySize, sm_l0);
    cudaFuncSetAttribute((const void*)gemm2<64,64,false>, cudaFuncAttributeMaxDynamicSharedMemorySize, sm_cv);
    cudaFuncSetAttribute((const void*)gemm2<64,32,true>,  cudaFuncAttributeMaxDynamicSharedMemorySize, sm_l1);
    cudaFuncSetAttribute((const void*)gemm2<32,16,true>,  cudaFuncAttributeMaxDynamicSharedMemorySize, sm_l2);
    cudaFuncSetAttribute((const void*)ygemm, cudaFuncAttributeMaxDynamicSharedMemorySize, sm_yg);

    const float invP = 1.f / (float)Pn;
    const float invQ = 1.f / (float)Qn;

    zero_stats<<<1, 512>>>(st);

    // ---- ScoreNet chain ----
    gemm2<66,64,false><<<Pn/256, 256, sm_l0>>>(
        xyz, sw0, nullptr, s0, st + 128, st + 192, Pn, 131072, 66L*131072);
    finalize_bn<<<1, 64>>>(st + 128, st + 192, sg0, sb0, ab + 128, 64, invP);

    gemm2<64,32,true><<<Pn/256, 256, sm_l1>>>(
        s0, sw1, ab + 128, s1, st + 256, st + 288, Pn, Pn, 0L);
    finalize_bn<<<1, 32>>>(st + 256, st + 288, sg1, sb1, ab + 256, 32, invP);

    gemm2<32,16,true><<<Pn/256, 256, sm_l2>>>(
        s1, sw2, ab + 256, s2, st + 320, st + 336, Pn, Pn, 0L);
    finalize_bn<<<1, 16>>>(st + 320, st + 336, sg2, sb2, ab + 320, 16, invP);

    l3_softmax<<<Pn/256, 256>>>(s2, sw3, sbs3, ab + 320, score);

    // ---- main path ----
    gemm2<64,64,false><<<Qn/256, 256, sm_cv>>>(
        x, w1, nullptr, h, st + 0, st + 64, Qn, 4096, 64L*4096);
    finalize_bn<<<1, 64>>>(st + 0, st + 64, bn1g, bn1b, ab + 0, 64, invQ);

    ygemm<<<dim3(Qn/128, 8), 256, sm_yg>>>(h, m2, ab + 0, y);

    // ---- gather + bn2 ----
    gather_k<<<Qn, 64>>>(y, score, idx, outr, st + 352, st + 416);
    finalize_bn<<<1, 64>>>(st + 352, st + 416, bn2g, bn2b, ab + 352, 64, invQ);
    apply_bn2<<<4096, 256>>>(outr, ab + 352, out);
}